// round 7
// baseline (speedup 1.0000x reference)
#include <cuda_runtime.h>
#include <cuda_fp16.h>
#include <mma.h>

using namespace nvcuda;

#define N_NODES 100000
#define N_EDGES 3200000
#define CH      128
#define NG      256
#define NC      32
#define APAD    136   // half elements per smem row (128 + 8)

// ---------------- scratch ----------------
__device__ __half g_y16[(size_t)N_NODES * CH]; // (x@W)*dinv[row], fp16
__device__ __half g_h[(size_t)N_NODES * CH];   // layer output, fp16
__device__ float  g_dinv[N_NODES];
__device__ int    g_deg[N_NODES];
__device__ int    g_rowptr[N_NODES + 1];
__device__ int    g_cursor[N_NODES];
__device__ int    g_csrc[N_EDGES];
__device__ float  g_pool[NG * CH];

// ---------------- CSR construction ----------------
__global__ void init_deg_k() {
    int v = blockIdx.x * blockDim.x + threadIdx.x;
    if (v < N_NODES) g_deg[v] = 1;   // self-loop
}

__global__ void hist_k(const int4* __restrict__ dst4) {
    int stride = gridDim.x * blockDim.x;
    for (int e = blockIdx.x * blockDim.x + threadIdx.x; e < N_EDGES / 4; e += stride) {
        int4 d = dst4[e];
        atomicAdd(&g_deg[d.x], 1);
        atomicAdd(&g_deg[d.y], 1);
        atomicAdd(&g_deg[d.z], 1);
        atomicAdd(&g_deg[d.w], 1);
    }
}

__global__ void scan_k() {
    __shared__ int ssum[1024];
    const int CHUNK = (N_NODES + 1023) / 1024;
    int t  = threadIdx.x;
    int lo = t * CHUNK;
    int hi = min(lo + CHUNK, N_NODES);
    int s = 0;
    for (int v = lo; v < hi; v++) s += g_deg[v] - 1;
    ssum[t] = s;
    __syncthreads();
    for (int off = 1; off < 1024; off <<= 1) {
        int val = (t >= off) ? ssum[t - off] : 0;
        __syncthreads();
        ssum[t] += val;
        __syncthreads();
    }
    int run = (t == 0) ? 0 : ssum[t - 1];
    for (int v = lo; v < hi; v++) {
        g_rowptr[v] = run;
        g_cursor[v] = run;
        int d = g_deg[v];
        run += d - 1;
        g_dinv[v] = rsqrtf((float)d);
    }
    if (t == 1023) g_rowptr[N_NODES] = N_EDGES;
}

__global__ void fill_k(const int4* __restrict__ src4, const int4* __restrict__ dst4) {
    int stride = gridDim.x * blockDim.x;
    for (int e = blockIdx.x * blockDim.x + threadIdx.x; e < N_EDGES / 4; e += stride) {
        int4 s = src4[e];
        int4 d = dst4[e];
        int p0 = atomicAdd(&g_cursor[d.x], 1);
        int p1 = atomicAdd(&g_cursor[d.y], 1);
        int p2 = atomicAdd(&g_cursor[d.z], 1);
        int p3 = atomicAdd(&g_cursor[d.w], 1);
        g_csrc[p0] = s.x;
        g_csrc[p1] = s.y;
        g_csrc[p2] = s.z;
        g_csrc[p3] = s.w;
    }
}

// ---------------- GEMM (tensor core): g_y16 = half((A @ W) * dinv[row]) ----------------
// 128x128 block tile, K=128 smem-resident fp16. B kept row-major [k][n] (no transpose).
#define GEMM_SMEM (2 * 128 * APAD * 2)

template <int A_IS_HALF>
__global__ void __launch_bounds__(256) gemm_wmma_k(
    const float* __restrict__ Af, const float* __restrict__ W, int M)
{
    extern __shared__ char smraw[];
    __half* As = (__half*)smraw;                         // [128][APAD], A[m][k]
    __half* Bs = (__half*)(smraw + 128 * APAD * 2);      // [128][APAD], B[k][n] = W
    float*  Cs = (float*)smraw;                          // [128][128] staging (reused)

    int tid = threadIdx.x;

    // W -> Bs straight copy+convert, vectorized (no transpose)
    for (int i = tid; i < 128 * 32; i += 256) {
        int k = i >> 5, c4 = i & 31;
        float4 v = *(const float4*)&W[k * 128 + c4 * 4];
        __half2 h0 = __floats2half2_rn(v.x, v.y);
        __half2 h1 = __floats2half2_rn(v.z, v.w);
        *(uint2*)&Bs[k * APAD + c4 * 4] = make_uint2(*(unsigned*)&h0, *(unsigned*)&h1);
    }

    // A tile -> As
    int row0 = blockIdx.x * 128;
    if (A_IS_HALF) {
        const __half* Ah = g_h;
        for (int i = tid; i < 128 * 16; i += 256) {
            int r = i >> 4, c8 = i & 15;
            uint4 v = make_uint4(0u, 0u, 0u, 0u);
            if (row0 + r < M) v = *(const uint4*)&Ah[(size_t)(row0 + r) * CH + c8 * 8];
            *(uint4*)&As[r * APAD + c8 * 8] = v;
        }
    } else {
        for (int i = tid; i < 128 * 32; i += 256) {
            int r = i >> 5, c4 = i & 31;
            float4 v = make_float4(0.f, 0.f, 0.f, 0.f);
            if (row0 + r < M) v = *(const float4*)&Af[(size_t)(row0 + r) * CH + c4 * 4];
            __half2 h0 = __floats2half2_rn(v.x, v.y);
            __half2 h1 = __floats2half2_rn(v.z, v.w);
            *(uint2*)&As[r * APAD + c4 * 4] = make_uint2(*(unsigned*)&h0, *(unsigned*)&h1);
        }
    }
    __syncthreads();

    int wid = tid >> 5;
    int wm = wid >> 2, wn = wid & 3;       // 2 x 4 warp grid
    int wrow = wm * 64, wcol = wn * 32;

    wmma::fragment<wmma::accumulator, 16, 16, 16, float> c[4][2];
    #pragma unroll
    for (int i = 0; i < 4; i++)
        #pragma unroll
        for (int j = 0; j < 2; j++) wmma::fill_fragment(c[i][j], 0.f);

    #pragma unroll
    for (int kk = 0; kk < 128; kk += 16) {
        wmma::fragment<wmma::matrix_a, 16, 16, 16, __half, wmma::row_major> a[4];
        wmma::fragment<wmma::matrix_b, 16, 16, 16, __half, wmma::row_major> b[2];
        #pragma unroll
        for (int i = 0; i < 4; i++)
            wmma::load_matrix_sync(a[i], As + (wrow + i * 16) * APAD + kk, APAD);
        #pragma unroll
        for (int j = 0; j < 2; j++)
            wmma::load_matrix_sync(b[j], Bs + kk * APAD + wcol + j * 16, APAD);
        #pragma unroll
        for (int i = 0; i < 4; i++)
            #pragma unroll
            for (int j = 0; j < 2; j++)
                wmma::mma_sync(c[i][j], a[i], b[j], c[i][j]);
    }

    __syncthreads();
    #pragma unroll
    for (int i = 0; i < 4; i++)
        #pragma unroll
        for (int j = 0; j < 2; j++)
            wmma::store_matrix_sync(Cs + (wrow + i * 16) * 128 + wcol + j * 16,
                                    c[i][j], 128, wmma::mem_row_major);
    __syncthreads();

    for (int i = tid; i < 128 * 16; i += 256) {
        int r = i >> 4, c8 = i & 15;
        int gr = row0 + r;
        if (gr < M) {
            float dv = g_dinv[gr];
            const float* s = &Cs[r * 128 + c8 * 8];
            __half2 p0 = __floats2half2_rn(s[0] * dv, s[1] * dv);
            __half2 p1 = __floats2half2_rn(s[2] * dv, s[3] * dv);
            __half2 p2 = __floats2half2_rn(s[4] * dv, s[5] * dv);
            __half2 p3 = __floats2half2_rn(s[6] * dv, s[7] * dv);
            *(uint4*)&g_y16[(size_t)gr * CH + c8 * 8] =
                make_uint4(*(unsigned*)&p0, *(unsigned*)&p1,
                           *(unsigned*)&p2, *(unsigned*)&p3);
        }
    }
}

// ---------------- aggregation: 2 nodes/warp, 16 lanes/node, LDG.128 ----------------
__device__ __forceinline__ void accum8(float* a, uint4 u) {
    float2 f0 = __half22float2(*(__half2*)&u.x);
    float2 f1 = __half22float2(*(__half2*)&u.y);
    float2 f2 = __half22float2(*(__half2*)&u.z);
    float2 f3 = __half22float2(*(__half2*)&u.w);
    a[0] += f0.x; a[1] += f0.y; a[2] += f1.x; a[3] += f1.y;
    a[4] += f2.x; a[5] += f2.y; a[6] += f3.x; a[7] += f3.y;
}

__global__ void __launch_bounds__(256) aggregate_k(const float* __restrict__ bias) {
    int warp_id = (blockIdx.x * blockDim.x + threadIdx.x) >> 5;
    int lane = threadIdx.x & 31;
    int l16  = lane & 15;
    int node = warp_id * 2 + (lane >> 4);           // each half-warp owns one node
    bool node_ok = node < N_NODES;
    int nc = node_ok ? node : 0;

    const uint4* y4 = (const uint4*)g_y16;          // row = 16 uint4 (256 B)

    float acc[8] = {0.f, 0.f, 0.f, 0.f, 0.f, 0.f, 0.f, 0.f};
    accum8(acc, y4[(size_t)nc * 16 + l16]);         // self-loop

    int beg = g_rowptr[nc];
    int cnt = node_ok ? (g_rowptr[nc + 1] - beg) : 0;
    int mc  = max(cnt, __shfl_xor_sync(0xffffffffu, cnt, 16));
    int begc = min(beg, N_EDGES - 1);

    for (int base = 0; base < mc; base += 16) {
        int pos = base + l16;
        int idx = g_csrc[(pos < cnt) ? (beg + pos) : begc];
        #pragma unroll
        for (int j = 0; j < 16; j++) {
            int s = __shfl_sync(0xffffffffu, idx, (lane & 16) + j);
            if (base + j < cnt) {                    // uniform per half-warp
                accum8(acc, y4[(size_t)s * 16 + l16]);
            }
        }
    }

    if (!node_ok) return;
    float dv = g_dinv[node];
    float4 b0 = ((const float4*)bias)[l16 * 2];
    float4 b1 = ((const float4*)bias)[l16 * 2 + 1];
    float r0 = fmaxf(fmaf(acc[0], dv, b0.x), 0.f);
    float r1 = fmaxf(fmaf(acc[1], dv, b0.y), 0.f);
    float r2 = fmaxf(fmaf(acc[2], dv, b0.z), 0.f);
    float r3 = fmaxf(fmaf(acc[3], dv, b0.w), 0.f);
    float r4 = fmaxf(fmaf(acc[4], dv, b1.x), 0.f);
    float r5 = fmaxf(fmaf(acc[5], dv, b1.y), 0.f);
    float r6 = fmaxf(fmaf(acc[6], dv, b1.z), 0.f);
    float r7 = fmaxf(fmaf(acc[7], dv, b1.w), 0.f);
    __half2 h0 = __floats2half2_rn(r0, r1);
    __half2 h1 = __floats2half2_rn(r2, r3);
    __half2 h2 = __floats2half2_rn(r4, r5);
    __half2 h3 = __floats2half2_rn(r6, r7);
    ((uint4*)g_h)[(size_t)node * 16 + l16] =
        make_uint4(*(unsigned*)&h0, *(unsigned*)&h1,
                   *(unsigned*)&h2, *(unsigned*)&h3);
}

// ---------------- pooling + FC ----------------
__device__ __forceinline__ int lower_bound_i(const int* a, int n, int key) {
    int lo = 0, hi = n;
    while (lo < hi) { int mid = (lo + hi) >> 1; if (a[mid] < key) lo = mid + 1; else hi = mid; }
    return lo;
}

__global__ void pool_k(const int* __restrict__ batch) {
    int g = blockIdx.x;
    __shared__ int slo, shi;
    if (threadIdx.x == 0) {
        slo = lower_bound_i(batch, N_NODES, g);
        shi = lower_bound_i(batch, N_NODES, g + 1);
    }
    __syncthreads();
    int lo = slo, hi = shi;
    int c = threadIdx.x;  // 128 threads
    float s = 0.f;
    for (int r = lo; r < hi; r++) s += __half2float(g_h[(size_t)r * CH + c]);
    float cnt = (float)(hi - lo);
    g_pool[g * CH + c] = s / fmaxf(cnt, 1.0f);
}

__global__ void fc_k(const float* __restrict__ Wfc, const float* __restrict__ bfc,
                     float* __restrict__ out) {
    int g = blockIdx.x;
    int c = threadIdx.x;
    float acc = bfc[c];
    #pragma unroll 4
    for (int k = 0; k < CH; k++)
        acc = fmaf(g_pool[g * CH + k], Wfc[k * NC + c], acc);
    out[g * NC + c] = acc;
}

// ---------------- launcher ----------------
extern "C" void kernel_launch(void* const* d_in, const int* in_sizes, int n_in,
                              void* d_out, int out_size) {
    const float* x     = (const float*)d_in[0];
    const int*   ei    = (const int*)  d_in[1];
    const int*   batch = (const int*)  d_in[2];
    const float* W1    = (const float*)d_in[3];
    const float* b1    = (const float*)d_in[4];
    const float* W2    = (const float*)d_in[5];
    const float* b2    = (const float*)d_in[6];
    const float* Wfc   = (const float*)d_in[7];
    const float* bfc   = (const float*)d_in[8];
    float* out = (float*)d_out;

    const int4* src4 = (const int4*)ei;
    const int4* dst4 = (const int4*)(ei + N_EDGES);

    cudaFuncSetAttribute(gemm_wmma_k<0>,
                         cudaFuncAttributeMaxDynamicSharedMemorySize, GEMM_SMEM);
    cudaFuncSetAttribute(gemm_wmma_k<1>,
                         cudaFuncAttributeMaxDynamicSharedMemorySize, GEMM_SMEM);

    // CSR build
    init_deg_k<<<(N_NODES + 255) / 256, 256>>>();
    hist_k<<<1024, 256>>>(dst4);
    scan_k<<<1, 1024>>>();
    fill_k<<<1024, 256>>>(src4, dst4);

    int gemm_blocks = (N_NODES + 127) / 128;
    int agg_warps   = (N_NODES + 1) / 2;
    int agg_blocks  = (agg_warps * 32 + 255) / 256;

    // layer 1
    gemm_wmma_k<0><<<gemm_blocks, 256, GEMM_SMEM>>>(x, W1, N_NODES);
    aggregate_k<<<agg_blocks, 256>>>(b1);
    // layer 2
    gemm_wmma_k<1><<<gemm_blocks, 256, GEMM_SMEM>>>(nullptr, W2, N_NODES);
    aggregate_k<<<agg_blocks, 256>>>(b2);
    // pool + fc
    pool_k<<<NG, 128>>>(batch);
    fc_k<<<NG, NC>>>(Wfc, bfc, out);
}

// round 8
// speedup vs baseline: 1.0580x; 1.0580x over previous
#include <cuda_runtime.h>
#include <cuda_fp16.h>
#include <mma.h>

using namespace nvcuda;

#define N_NODES 100000
#define N_EDGES 3200000
#define CH      128
#define NG      256
#define NC      32
#define APAD    136   // half elements per smem row (128 + 8)

// ---------------- scratch ----------------
__device__ __half g_y16[(size_t)N_NODES * CH]; // (x@W)*dinv[row], fp16
__device__ __half g_h[(size_t)N_NODES * CH];   // layer output, fp16
__device__ float  g_dinv[N_NODES];
__device__ int    g_deg[N_NODES];
__device__ int    g_rowptr[N_NODES + 1];
__device__ int    g_cursor[N_NODES];
__device__ int    g_csrc[N_EDGES];
__device__ float  g_pool[NG * CH];

// ---------------- CSR construction ----------------
__global__ void init_deg_k() {
    int v = blockIdx.x * blockDim.x + threadIdx.x;
    if (v < N_NODES) g_deg[v] = 1;   // self-loop
}

__global__ void hist_k(const int4* __restrict__ dst4) {
    int stride = gridDim.x * blockDim.x;
    int i = blockIdx.x * blockDim.x + threadIdx.x;
    // 2 int4 chunks per iteration -> 8 independent atomics in flight
    for (; i + stride < N_EDGES / 4; i += 2 * stride) {
        int4 d0 = dst4[i];
        int4 d1 = dst4[i + stride];
        atomicAdd(&g_deg[d0.x], 1);
        atomicAdd(&g_deg[d0.y], 1);
        atomicAdd(&g_deg[d0.z], 1);
        atomicAdd(&g_deg[d0.w], 1);
        atomicAdd(&g_deg[d1.x], 1);
        atomicAdd(&g_deg[d1.y], 1);
        atomicAdd(&g_deg[d1.z], 1);
        atomicAdd(&g_deg[d1.w], 1);
    }
    if (i < N_EDGES / 4) {
        int4 d = dst4[i];
        atomicAdd(&g_deg[d.x], 1);
        atomicAdd(&g_deg[d.y], 1);
        atomicAdd(&g_deg[d.z], 1);
        atomicAdd(&g_deg[d.w], 1);
    }
}

__global__ void scan_k() {
    __shared__ int ssum[1024];
    const int CHUNK = (N_NODES + 1023) / 1024;
    int t  = threadIdx.x;
    int lo = t * CHUNK;
    int hi = min(lo + CHUNK, N_NODES);
    int s = 0;
    for (int v = lo; v < hi; v++) s += g_deg[v] - 1;
    ssum[t] = s;
    __syncthreads();
    for (int off = 1; off < 1024; off <<= 1) {
        int val = (t >= off) ? ssum[t - off] : 0;
        __syncthreads();
        ssum[t] += val;
        __syncthreads();
    }
    int run = (t == 0) ? 0 : ssum[t - 1];
    for (int v = lo; v < hi; v++) {
        g_rowptr[v] = run;
        g_cursor[v] = run;
        int d = g_deg[v];
        run += d - 1;
        g_dinv[v] = rsqrtf((float)d);
    }
    if (t == 1023) g_rowptr[N_NODES] = N_EDGES;
}

__global__ void fill_k(const int4* __restrict__ src4, const int4* __restrict__ dst4) {
    int stride = gridDim.x * blockDim.x;
    int i = blockIdx.x * blockDim.x + threadIdx.x;
    for (; i + stride < N_EDGES / 4; i += 2 * stride) {
        int4 s0 = src4[i];
        int4 d0 = dst4[i];
        int4 s1 = src4[i + stride];
        int4 d1 = dst4[i + stride];
        int p0 = atomicAdd(&g_cursor[d0.x], 1);
        int p1 = atomicAdd(&g_cursor[d0.y], 1);
        int p2 = atomicAdd(&g_cursor[d0.z], 1);
        int p3 = atomicAdd(&g_cursor[d0.w], 1);
        int p4 = atomicAdd(&g_cursor[d1.x], 1);
        int p5 = atomicAdd(&g_cursor[d1.y], 1);
        int p6 = atomicAdd(&g_cursor[d1.z], 1);
        int p7 = atomicAdd(&g_cursor[d1.w], 1);
        g_csrc[p0] = s0.x;
        g_csrc[p1] = s0.y;
        g_csrc[p2] = s0.z;
        g_csrc[p3] = s0.w;
        g_csrc[p4] = s1.x;
        g_csrc[p5] = s1.y;
        g_csrc[p6] = s1.z;
        g_csrc[p7] = s1.w;
    }
    if (i < N_EDGES / 4) {
        int4 s = src4[i];
        int4 d = dst4[i];
        int p0 = atomicAdd(&g_cursor[d.x], 1);
        int p1 = atomicAdd(&g_cursor[d.y], 1);
        int p2 = atomicAdd(&g_cursor[d.z], 1);
        int p3 = atomicAdd(&g_cursor[d.w], 1);
        g_csrc[p0] = s.x;
        g_csrc[p1] = s.y;
        g_csrc[p2] = s.z;
        g_csrc[p3] = s.w;
    }
}

// ---------------- GEMM (tensor core): g_y16 = half((A @ W) * dinv[row]) ----------------
// 128x128 block tile, K=128 smem-resident fp16, B row-major [k][n] (no transpose).
#define GEMM_SMEM (2 * 128 * APAD * 2)

template <int A_IS_HALF>
__global__ void __launch_bounds__(256) gemm_wmma_k(
    const float* __restrict__ Af, const float* __restrict__ W, int M)
{
    extern __shared__ char smraw[];
    __half* As = (__half*)smraw;                         // [128][APAD], A[m][k]
    __half* Bs = (__half*)(smraw + 128 * APAD * 2);      // [128][APAD], B[k][n] = W
    float*  Cs = (float*)smraw;                          // [128][128] staging (reused)

    int tid = threadIdx.x;

    // W -> Bs straight copy+convert, vectorized (no transpose)
    for (int i = tid; i < 128 * 32; i += 256) {
        int k = i >> 5, c4 = i & 31;
        float4 v = *(const float4*)&W[k * 128 + c4 * 4];
        __half2 h0 = __floats2half2_rn(v.x, v.y);
        __half2 h1 = __floats2half2_rn(v.z, v.w);
        *(uint2*)&Bs[k * APAD + c4 * 4] = make_uint2(*(unsigned*)&h0, *(unsigned*)&h1);
    }

    // A tile -> As
    int row0 = blockIdx.x * 128;
    if (A_IS_HALF) {
        const __half* Ah = g_h;
        for (int i = tid; i < 128 * 16; i += 256) {
            int r = i >> 4, c8 = i & 15;
            uint4 v = make_uint4(0u, 0u, 0u, 0u);
            if (row0 + r < M) v = *(const uint4*)&Ah[(size_t)(row0 + r) * CH + c8 * 8];
            *(uint4*)&As[r * APAD + c8 * 8] = v;
        }
    } else {
        for (int i = tid; i < 128 * 32; i += 256) {
            int r = i >> 5, c4 = i & 31;
            float4 v = make_float4(0.f, 0.f, 0.f, 0.f);
            if (row0 + r < M) v = *(const float4*)&Af[(size_t)(row0 + r) * CH + c4 * 4];
            __half2 h0 = __floats2half2_rn(v.x, v.y);
            __half2 h1 = __floats2half2_rn(v.z, v.w);
            *(uint2*)&As[r * APAD + c4 * 4] = make_uint2(*(unsigned*)&h0, *(unsigned*)&h1);
        }
    }
    __syncthreads();

    int wid = tid >> 5;
    int wm = wid >> 2, wn = wid & 3;       // 2 x 4 warp grid
    int wrow = wm * 64, wcol = wn * 32;

    wmma::fragment<wmma::accumulator, 16, 16, 16, float> c[4][2];
    #pragma unroll
    for (int i = 0; i < 4; i++)
        #pragma unroll
        for (int j = 0; j < 2; j++) wmma::fill_fragment(c[i][j], 0.f);

    #pragma unroll
    for (int kk = 0; kk < 128; kk += 16) {
        wmma::fragment<wmma::matrix_a, 16, 16, 16, __half, wmma::row_major> a[4];
        wmma::fragment<wmma::matrix_b, 16, 16, 16, __half, wmma::row_major> b[2];
        #pragma unroll
        for (int i = 0; i < 4; i++)
            wmma::load_matrix_sync(a[i], As + (wrow + i * 16) * APAD + kk, APAD);
        #pragma unroll
        for (int j = 0; j < 2; j++)
            wmma::load_matrix_sync(b[j], Bs + kk * APAD + wcol + j * 16, APAD);
        #pragma unroll
        for (int i = 0; i < 4; i++)
            #pragma unroll
            for (int j = 0; j < 2; j++)
                wmma::mma_sync(c[i][j], a[i], b[j], c[i][j]);
    }

    __syncthreads();
    #pragma unroll
    for (int i = 0; i < 4; i++)
        #pragma unroll
        for (int j = 0; j < 2; j++)
            wmma::store_matrix_sync(Cs + (wrow + i * 16) * 128 + wcol + j * 16,
                                    c[i][j], 128, wmma::mem_row_major);
    __syncthreads();

    for (int i = tid; i < 128 * 16; i += 256) {
        int r = i >> 4, c8 = i & 15;
        int gr = row0 + r;
        if (gr < M) {
            float dv = g_dinv[gr];
            const float* s = &Cs[r * 128 + c8 * 8];
            __half2 p0 = __floats2half2_rn(s[0] * dv, s[1] * dv);
            __half2 p1 = __floats2half2_rn(s[2] * dv, s[3] * dv);
            __half2 p2 = __floats2half2_rn(s[4] * dv, s[5] * dv);
            __half2 p3 = __floats2half2_rn(s[6] * dv, s[7] * dv);
            *(uint4*)&g_y16[(size_t)gr * CH + c8 * 8] =
                make_uint4(*(unsigned*)&p0, *(unsigned*)&p1,
                           *(unsigned*)&p2, *(unsigned*)&p3);
        }
    }
}

// ---------------- aggregation (R6 form): warp per node, uint2/lane ----------------
__device__ __forceinline__ void acc4(float4& a, uint2 u) {
    float2 f0 = __half22float2(*(__half2*)&u.x);
    float2 f1 = __half22float2(*(__half2*)&u.y);
    a.x += f0.x; a.y += f0.y; a.z += f1.x; a.w += f1.y;
}

__global__ void __launch_bounds__(256) aggregate_k(const float* __restrict__ bias) {
    int w = (blockIdx.x * blockDim.x + threadIdx.x) >> 5;
    if (w >= N_NODES) return;
    int lane = threadIdx.x & 31;

    const uint2* y2 = (const uint2*)g_y16;   // row stride = 32 uint2

    float4 a0 = make_float4(0.f, 0.f, 0.f, 0.f);
    float4 a1 = make_float4(0.f, 0.f, 0.f, 0.f);
    acc4(a0, y2[(size_t)w * 32 + lane]);     // self-loop

    int beg = g_rowptr[w], end = g_rowptr[w + 1];
    int i = beg;
    for (; i + 32 <= end; i += 32) {
        int idx = g_csrc[i + lane];
        #pragma unroll
        for (int j = 0; j < 32; j += 2) {
            int s0 = __shfl_sync(0xffffffffu, idx, j);
            int s1 = __shfl_sync(0xffffffffu, idx, j + 1);
            uint2 u0 = y2[(size_t)s0 * 32 + lane];
            uint2 u1 = y2[(size_t)s1 * 32 + lane];
            acc4(a0, u0);
            acc4(a1, u1);
        }
    }
    if (i < end) {
        int cnt = end - i;
        int idx = g_csrc[min(i + lane, end - 1)];
        for (int j = 0; j < cnt; j++) {
            int s = __shfl_sync(0xffffffffu, idx, j);
            acc4(a0, y2[(size_t)s * 32 + lane]);
        }
    }

    float dv = g_dinv[w];
    float4 b = ((const float4*)bias)[lane];
    float rx = fmaxf(fmaf(a0.x + a1.x, dv, b.x), 0.f);
    float ry = fmaxf(fmaf(a0.y + a1.y, dv, b.y), 0.f);
    float rz = fmaxf(fmaf(a0.z + a1.z, dv, b.z), 0.f);
    float rw = fmaxf(fmaf(a0.w + a1.w, dv, b.w), 0.f);
    __half2 h0 = __floats2half2_rn(rx, ry);
    __half2 h1 = __floats2half2_rn(rz, rw);
    ((uint2*)g_h)[(size_t)w * 32 + lane] =
        make_uint2(*(unsigned*)&h0, *(unsigned*)&h1);
}

// ---------------- pooling + FC ----------------
__device__ __forceinline__ int lower_bound_i(const int* a, int n, int key) {
    int lo = 0, hi = n;
    while (lo < hi) { int mid = (lo + hi) >> 1; if (a[mid] < key) lo = mid + 1; else hi = mid; }
    return lo;
}

__global__ void pool_k(const int* __restrict__ batch) {
    int g = blockIdx.x;
    __shared__ int slo, shi;
    if (threadIdx.x == 0) {
        slo = lower_bound_i(batch, N_NODES, g);
        shi = lower_bound_i(batch, N_NODES, g + 1);
    }
    __syncthreads();
    int lo = slo, hi = shi;
    int c = threadIdx.x;  // 128 threads
    float s = 0.f;
    for (int r = lo; r < hi; r++) s += __half2float(g_h[(size_t)r * CH + c]);
    float cnt = (float)(hi - lo);
    g_pool[g * CH + c] = s / fmaxf(cnt, 1.0f);
}

__global__ void fc_k(const float* __restrict__ Wfc, const float* __restrict__ bfc,
                     float* __restrict__ out) {
    int g = blockIdx.x;
    int c = threadIdx.x;
    float acc = bfc[c];
    #pragma unroll 4
    for (int k = 0; k < CH; k++)
        acc = fmaf(g_pool[g * CH + k], Wfc[k * NC + c], acc);
    out[g * NC + c] = acc;
}

// ---------------- launcher ----------------
extern "C" void kernel_launch(void* const* d_in, const int* in_sizes, int n_in,
                              void* d_out, int out_size) {
    const float* x     = (const float*)d_in[0];
    const int*   ei    = (const int*)  d_in[1];
    const int*   batch = (const int*)  d_in[2];
    const float* W1    = (const float*)d_in[3];
    const float* b1    = (const float*)d_in[4];
    const float* W2    = (const float*)d_in[5];
    const float* b2    = (const float*)d_in[6];
    const float* Wfc   = (const float*)d_in[7];
    const float* bfc   = (const float*)d_in[8];
    float* out = (float*)d_out;

    const int4* src4 = (const int4*)ei;
    const int4* dst4 = (const int4*)(ei + N_EDGES);

    static cudaStream_t s2 = nullptr;
    static cudaEvent_t  e0 = nullptr, e1 = nullptr;
    if (!s2) {
        cudaStreamCreate(&s2);
        cudaEventCreateWithFlags(&e0, cudaEventDisableTiming);
        cudaEventCreateWithFlags(&e1, cudaEventDisableTiming);
        cudaFuncSetAttribute(gemm_wmma_k<0>,
                             cudaFuncAttributeMaxDynamicSharedMemorySize, GEMM_SMEM);
        cudaFuncSetAttribute(gemm_wmma_k<1>,
                             cudaFuncAttributeMaxDynamicSharedMemorySize, GEMM_SMEM);
    }

    int gemm_blocks = (N_NODES + 127) / 128;
    int agg_blocks  = (N_NODES * 32 + 255) / 256;

    // serial prefix: deg + scan (produces dinv, rowptr, cursor)
    init_deg_k<<<(N_NODES + 255) / 256, 256>>>();
    hist_k<<<1184, 256>>>(dst4);
    scan_k<<<1, 1024>>>();

    // fork: fill_k (needs cursor) on s2, concurrent with gemm1 (needs only dinv)
    cudaEventRecord(e0, 0);
    cudaStreamWaitEvent(s2, e0, 0);
    fill_k<<<1184, 256, 0, s2>>>(src4, dst4);
    gemm_wmma_k<0><<<gemm_blocks, 256, GEMM_SMEM>>>(x, W1, N_NODES);
    cudaEventRecord(e1, s2);
    cudaStreamWaitEvent(0, e1, 0);

    // layer 1 aggregate (needs csrc + y)
    aggregate_k<<<agg_blocks, 256>>>(b1);
    // layer 2
    gemm_wmma_k<1><<<gemm_blocks, 256, GEMM_SMEM>>>(nullptr, W2, N_NODES);
    aggregate_k<<<agg_blocks, 256>>>(b2);
    // pool + fc
    pool_k<<<NG, 128>>>(batch);
    fc_k<<<NG, NC>>>(Wfc, bfc, out);
}